// round 3
// baseline (speedup 1.0000x reference)
#include <cuda_runtime.h>
#include <math.h>

#define kN  100000   // nodes
#define kE0 160000   // edges per mask segment
#define kE  800000   // total edges
#define kD  128      // embed dim
#define kH  8        // heads
#define kDK 16       // head dim
#define kNG 50       // gaussians
#define kSCALE 0.25f // 1/sqrt(16)
#define kEPS 1e-5f

typedef unsigned long long u64;

// ---------------- scratch (device globals; no runtime alloc) ----------------
__device__ float g_zk[kN * kD];        // 51.2 MB
__device__ float g_mask[kE * kH];      // 25.6 MB
__device__ float g_scores[kE * kH];    // 25.6 MB
__device__ float g_denom[kN * kH];     //  3.2 MB
__device__ float g_agg[kN * kD];       // 51.2 MB
__device__ float g_x1[kN * kD];        // 51.2 MB
__device__ float g_hbuf[kN * 2 * kD];  // 102.4 MB

// ---------------- helpers ----------------
__device__ __forceinline__ float warp_sum(float v) {
    v += __shfl_xor_sync(0xffffffffu, v, 16);
    v += __shfl_xor_sync(0xffffffffu, v, 8);
    v += __shfl_xor_sync(0xffffffffu, v, 4);
    v += __shfl_xor_sync(0xffffffffu, v, 2);
    v += __shfl_xor_sync(0xffffffffu, v, 1);
    return v;
}

__device__ __forceinline__ float gelu_tanh(float v) {
    float c = v + 0.044715f * v * v * v;
    return 0.5f * v * (1.0f + tanhf(0.7978845608028654f * c));
}

// packed f32x2 ops
__device__ __forceinline__ u64 dup2(float v) {
    u64 r;
    asm("mov.b64 %0, {%1, %1};" : "=l"(r) : "f"(v));
    return r;
}
__device__ __forceinline__ u64 ffma2(u64 a, u64 b, u64 c) {
    u64 d;
    asm("fma.rn.f32x2 %0, %1, %2, %3;" : "=l"(d) : "l"(a), "l"(b), "l"(c));
    return d;
}
__device__ __forceinline__ u64 fadd2(u64 a, u64 b) {
    u64 d;
    asm("add.rn.f32x2 %0, %1, %2;" : "=l"(d) : "l"(a), "l"(b));
    return d;
}
union F2U { u64 u; float2 f; };

// ---------------- K0: zero denom + agg ----------------
__global__ void k_init() {
    int idx = blockIdx.x * blockDim.x + threadIdx.x;
    int stride = gridDim.x * blockDim.x;
    for (int i = idx; i < kN * kH; i += stride) g_denom[i] = 0.0f;
    for (int i = idx; i < kN * kD; i += stride) g_agg[i] = 0.0f;
}

// ---------------- K1: zk = LN1(x) @ Wk + bk ----------------
// 256 threads, 32 rows/block, each warp 4 rows, each thread 4 cols (2 packed pairs).
__global__ void k_ln_gemm(const float* __restrict__ x, const float* __restrict__ W,
                          const float* __restrict__ bias, const float* __restrict__ gam,
                          const float* __restrict__ bet) {
    __shared__ float zs[32][128];
    const int tid = threadIdx.x;
    const int w = tid >> 5, l = tid & 31;
    const int row0 = blockIdx.x << 5;
    const int rb = w << 2;

    const float4 gm = reinterpret_cast<const float4*>(gam)[l];
    const float4 bt = reinterpret_cast<const float4*>(bet)[l];
#pragma unroll
    for (int j = 0; j < 4; j++) {
        int r = rb + j;
        float4 xv = reinterpret_cast<const float4*>(x + (size_t)(row0 + r) * kD)[l];
        float s = xv.x + xv.y + xv.z + xv.w;
        float ss = xv.x * xv.x + xv.y * xv.y + xv.z * xv.z + xv.w * xv.w;
        s = warp_sum(s); ss = warp_sum(ss);
        float mu = s * (1.0f / 128.0f);
        float var = ss * (1.0f / 128.0f) - mu * mu;
        float rstd = rsqrtf(var + kEPS);
        float4 z;
        z.x = (xv.x - mu) * rstd * gm.x + bt.x;
        z.y = (xv.y - mu) * rstd * gm.y + bt.y;
        z.z = (xv.z - mu) * rstd * gm.z + bt.z;
        z.w = (xv.w - mu) * rstd * gm.w + bt.w;
        *reinterpret_cast<float4*>(&zs[r][l << 2]) = z;
    }
    __syncthreads();

    const ulonglong2* W2p = reinterpret_cast<const ulonglong2*>(W);
    ulonglong2 bv = reinterpret_cast<const ulonglong2*>(bias)[l];
    u64 a00 = bv.x, a01 = bv.y, a10 = bv.x, a11 = bv.y;
    u64 a20 = bv.x, a21 = bv.y, a30 = bv.x, a31 = bv.y;
#pragma unroll 4
    for (int k = 0; k < 128; k++) {
        ulonglong2 wv = __ldg(&W2p[k * 32 + l]);
        u64 z0 = dup2(zs[rb + 0][k]);
        u64 z1 = dup2(zs[rb + 1][k]);
        u64 z2 = dup2(zs[rb + 2][k]);
        u64 z3 = dup2(zs[rb + 3][k]);
        a00 = ffma2(z0, wv.x, a00); a01 = ffma2(z0, wv.y, a01);
        a10 = ffma2(z1, wv.x, a10); a11 = ffma2(z1, wv.y, a11);
        a20 = ffma2(z2, wv.x, a20); a21 = ffma2(z2, wv.y, a21);
        a30 = ffma2(z3, wv.x, a30); a31 = ffma2(z3, wv.y, a31);
    }
    ulonglong2* o2 = reinterpret_cast<ulonglong2*>(g_zk + (size_t)(row0 + rb) * kD);
    o2[l] = make_ulonglong2(a00, a01);
    o2[32 + l] = make_ulonglong2(a10, a11);
    o2[64 + l] = make_ulonglong2(a20, a21);
    o2[96 + l] = make_ulonglong2(a30, a31);
}

// ---------------- K2: attention mask (gaussian smear + per-head linear) ----------------
__global__ void k_mask(const float* __restrict__ all_dist, const float* __restrict__ dist,
                       const float* __restrict__ cdd, const float* __restrict__ css,
                       const float* __restrict__ Wnn, const float* __restrict__ bnn,
                       const float* __restrict__ Wne, const float* __restrict__ bne,
                       const float* __restrict__ Wen, const float* __restrict__ ben,
                       const float* __restrict__ Wdd, const float* __restrict__ bdd,
                       const float* __restrict__ Wss, const float* __restrict__ bss) {
    __shared__ float Ws[kNG * kH];
    __shared__ float bs[kH];
    const int e0 = blockIdx.x << 8;
    const int seg = e0 / kE0;
    const float *Wp, *bp, *dp;
    float start, stop;
    if (seg == 0)      { Wp = Wnn; bp = bnn; dp = all_dist; start = 0.0f;  stop = 12.0f; }
    else if (seg == 1) { Wp = Wne; bp = bne; dp = dist;     start = 0.0f;  stop = 12.0f; }
    else if (seg == 2) { Wp = Wen; bp = ben; dp = dist;     start = 0.0f;  stop = 12.0f; }
    else if (seg == 3) { Wp = Wdd; bp = bdd; dp = cdd;      start = -1.0f; stop = 1.0f;  }
    else               { Wp = Wss; bp = bss; dp = css;      start = -1.0f; stop = 1.0f;  }
    for (int t = threadIdx.x; t < kNG * kH; t += 256) Ws[t] = Wp[t];
    if (threadIdx.x < kH) bs[threadIdx.x] = bp[threadIdx.x];
    __syncthreads();

    const int e = e0 + threadIdx.x;
    const float d = dp[e - seg * kE0];
    const float step = (stop - start) * (1.0f / 49.0f);
    const float coeff = -0.5f / (step * step);

    float a0 = bs[0], a1 = bs[1], a2 = bs[2], a3 = bs[3];
    float a4 = bs[4], a5 = bs[5], a6 = bs[6], a7 = bs[7];
#pragma unroll 5
    for (int g = 0; g < kNG; g++) {
        float t = d - (start + (float)g * step);
        float sm = expf(coeff * t * t);
        a0 += sm * Ws[g * 8 + 0]; a1 += sm * Ws[g * 8 + 1];
        a2 += sm * Ws[g * 8 + 2]; a3 += sm * Ws[g * 8 + 3];
        a4 += sm * Ws[g * 8 + 4]; a5 += sm * Ws[g * 8 + 5];
        a6 += sm * Ws[g * 8 + 6]; a7 += sm * Ws[g * 8 + 7];
    }
    float4* m4 = reinterpret_cast<float4*>(g_mask + (size_t)e * kH);
    m4[0] = make_float4(a0, a1, a2, a3);
    m4[1] = make_float4(a4, a5, a6, a7);
}

// ---------------- K3: warp-per-edge scores ----------------
// lane l loads float4 l of q row and kv row (fully coalesced 512B rows),
// quad shfl-reduce -> head dots, lanes 0-7 finalize.
__global__ void k_scores(const int* __restrict__ edges) {
    const int e = blockIdx.x * 8 + (threadIdx.x >> 5);
    const int l = threadIdx.x & 31;
    const int i = edges[e];
    const int j = edges[kE + e];
    const float4* zk4 = reinterpret_cast<const float4*>(g_zk);
    float4 q = zk4[(size_t)i * 32 + l];
    float4 k = zk4[(size_t)j * 32 + l];
    float d = q.x * k.x + q.y * k.y + q.z * k.z + q.w * k.w;
    d += __shfl_xor_sync(0xffffffffu, d, 1);
    d += __shfl_xor_sync(0xffffffffu, d, 2);     // quad sum: head = l>>2
    float dh = __shfl_sync(0xffffffffu, d, (l & 7) << 2);
    if (l < 8) {
        float sc = expf(kSCALE * dh + g_mask[(size_t)e * kH + l]);
        g_scores[(size_t)e * kH + l] = sc;
        atomicAdd(&g_denom[(size_t)i * kH + l], sc);
    }
}

// ---------------- K4: agg[seg] += (scores/denom) * kv ----------------
__global__ void k_scatter(const int* __restrict__ edges) {
    const int e = (blockIdx.x * blockDim.x + threadIdx.x) >> 5;
    const int l = threadIdx.x & 31;
    const int i = edges[e];
    const int j = edges[kE + e];
    float v = 0.0f;
    if (l < 8) v = g_scores[(size_t)e * kH + l] / g_denom[(size_t)i * kH + l];
    float s = __shfl_sync(0xffffffffu, v, l >> 2);
    float4 kv = reinterpret_cast<const float4*>(g_zk)[(size_t)j * 32 + l];
    float ox = s * kv.x, oy = s * kv.y, oz = s * kv.z, ow = s * kv.w;
    float* dst = g_agg + (size_t)i * kD + l * 4;
    asm volatile("red.global.add.v4.f32 [%0], {%1,%2,%3,%4};"
                 :: "l"(dst), "f"(ox), "f"(oy), "f"(oz), "f"(ow) : "memory");
}

// ---------------- K5: x1 = x + agg @ Wo + bo ----------------
__global__ void k_outproj(const float* __restrict__ x, const float* __restrict__ W,
                          const float* __restrict__ bias) {
    __shared__ float zs[32][128];
    const int tid = threadIdx.x;
    const int w = tid >> 5, l = tid & 31;
    const int row0 = blockIdx.x << 5;
    const int rb = w << 2;
#pragma unroll
    for (int j = 0; j < 4; j++) {
        int r = rb + j;
        float4 av = reinterpret_cast<const float4*>(g_agg + (size_t)(row0 + r) * kD)[l];
        *reinterpret_cast<float4*>(&zs[r][l << 2]) = av;
    }
    __syncthreads();

    const ulonglong2* W2p = reinterpret_cast<const ulonglong2*>(W);
    ulonglong2 bv = reinterpret_cast<const ulonglong2*>(bias)[l];
    u64 a00 = bv.x, a01 = bv.y, a10 = bv.x, a11 = bv.y;
    u64 a20 = bv.x, a21 = bv.y, a30 = bv.x, a31 = bv.y;
#pragma unroll 4
    for (int k = 0; k < 128; k++) {
        ulonglong2 wv = __ldg(&W2p[k * 32 + l]);
        u64 z0 = dup2(zs[rb + 0][k]);
        u64 z1 = dup2(zs[rb + 1][k]);
        u64 z2 = dup2(zs[rb + 2][k]);
        u64 z3 = dup2(zs[rb + 3][k]);
        a00 = ffma2(z0, wv.x, a00); a01 = ffma2(z0, wv.y, a01);
        a10 = ffma2(z1, wv.x, a10); a11 = ffma2(z1, wv.y, a11);
        a20 = ffma2(z2, wv.x, a20); a21 = ffma2(z2, wv.y, a21);
        a30 = ffma2(z3, wv.x, a30); a31 = ffma2(z3, wv.y, a31);
    }
    const ulonglong2* x2 = reinterpret_cast<const ulonglong2*>(x + (size_t)(row0 + rb) * kD);
    ulonglong2* o2 = reinterpret_cast<ulonglong2*>(g_x1 + (size_t)(row0 + rb) * kD);
    ulonglong2 xv;
    xv = x2[l];      o2[l]      = make_ulonglong2(fadd2(a00, xv.x), fadd2(a01, xv.y));
    xv = x2[32 + l]; o2[32 + l] = make_ulonglong2(fadd2(a10, xv.x), fadd2(a11, xv.y));
    xv = x2[64 + l]; o2[64 + l] = make_ulonglong2(fadd2(a20, xv.x), fadd2(a21, xv.y));
    xv = x2[96 + l]; o2[96 + l] = make_ulonglong2(fadd2(a30, xv.x), fadd2(a31, xv.y));
}

// ---------------- K6: h = gelu(LN2(x1) @ W1 + bf1) ---- grid.y = 128-col half ----
__global__ void k_ff1(const float* __restrict__ W1, const float* __restrict__ bias,
                      const float* __restrict__ gam, const float* __restrict__ bet) {
    __shared__ float zs[32][128];
    const int tid = threadIdx.x;
    const int w = tid >> 5, l = tid & 31;
    const int row0 = blockIdx.x << 5;
    const int colb4 = blockIdx.y << 5;   // col base / 4 : 0 or 32
    const int rb = w << 2;

    const float4 gm = reinterpret_cast<const float4*>(gam)[l];
    const float4 bt = reinterpret_cast<const float4*>(bet)[l];
#pragma unroll
    for (int j = 0; j < 4; j++) {
        int r = rb + j;
        float4 xv = reinterpret_cast<const float4*>(g_x1 + (size_t)(row0 + r) * kD)[l];
        float s = xv.x + xv.y + xv.z + xv.w;
        float ss = xv.x * xv.x + xv.y * xv.y + xv.z * xv.z + xv.w * xv.w;
        s = warp_sum(s); ss = warp_sum(ss);
        float mu = s * (1.0f / 128.0f);
        float var = ss * (1.0f / 128.0f) - mu * mu;
        float rstd = rsqrtf(var + kEPS);
        float4 z;
        z.x = (xv.x - mu) * rstd * gm.x + bt.x;
        z.y = (xv.y - mu) * rstd * gm.y + bt.y;
        z.z = (xv.z - mu) * rstd * gm.z + bt.z;
        z.w = (xv.w - mu) * rstd * gm.w + bt.w;
        *reinterpret_cast<float4*>(&zs[r][l << 2]) = z;
    }
    __syncthreads();

    const ulonglong2* W2p = reinterpret_cast<const ulonglong2*>(W1);
    ulonglong2 bv = reinterpret_cast<const ulonglong2*>(bias)[colb4 + l];
    u64 a00 = bv.x, a01 = bv.y, a10 = bv.x, a11 = bv.y;
    u64 a20 = bv.x, a21 = bv.y, a30 = bv.x, a31 = bv.y;
#pragma unroll 4
    for (int k = 0; k < 128; k++) {
        ulonglong2 wv = __ldg(&W2p[k * 64 + colb4 + l]);
        u64 z0 = dup2(zs[rb + 0][k]);
        u64 z1 = dup2(zs[rb + 1][k]);
        u64 z2 = dup2(zs[rb + 2][k]);
        u64 z3 = dup2(zs[rb + 3][k]);
        a00 = ffma2(z0, wv.x, a00); a01 = ffma2(z0, wv.y, a01);
        a10 = ffma2(z1, wv.x, a10); a11 = ffma2(z1, wv.y, a11);
        a20 = ffma2(z2, wv.x, a20); a21 = ffma2(z2, wv.y, a21);
        a30 = ffma2(z3, wv.x, a30); a31 = ffma2(z3, wv.y, a31);
    }
#pragma unroll
    for (int j = 0; j < 4; j++) {
        F2U p0, p1;
        p0.u = (j == 0) ? a00 : (j == 1) ? a10 : (j == 2) ? a20 : a30;
        p1.u = (j == 0) ? a01 : (j == 1) ? a11 : (j == 2) ? a21 : a31;
        float4 a;
        a.x = gelu_tanh(p0.f.x); a.y = gelu_tanh(p0.f.y);
        a.z = gelu_tanh(p1.f.x); a.w = gelu_tanh(p1.f.y);
        float* hp = g_hbuf + (size_t)(row0 + rb + j) * 256 + (colb4 << 2);
        reinterpret_cast<float4*>(hp)[l] = a;
    }
}

// ---------------- K7: out = x1 + h @ W2 + bf2 ----------------
__global__ void k_ff2(const float* __restrict__ W2, const float* __restrict__ bias,
                      float* __restrict__ out) {
    __shared__ float hs[32][256];
    const int tid = threadIdx.x;
    const int w = tid >> 5, l = tid & 31;
    const int row0 = blockIdx.x << 5;
    const int rb = w << 2;
#pragma unroll
    for (int j = 0; j < 4; j++) {
        int r = rb + j;
        const float4* hp = reinterpret_cast<const float4*>(g_hbuf + (size_t)(row0 + r) * 256);
        *reinterpret_cast<float4*>(&hs[r][l << 2]) = hp[l];
        *reinterpret_cast<float4*>(&hs[r][128 + (l << 2)]) = hp[32 + l];
    }
    __syncthreads();

    const ulonglong2* W2p = reinterpret_cast<const ulonglong2*>(W2);
    ulonglong2 bv = reinterpret_cast<const ulonglong2*>(bias)[l];
    u64 a00 = bv.x, a01 = bv.y, a10 = bv.x, a11 = bv.y;
    u64 a20 = bv.x, a21 = bv.y, a30 = bv.x, a31 = bv.y;
#pragma unroll 4
    for (int k = 0; k < 256; k++) {
        ulonglong2 wv = __ldg(&W2p[k * 32 + l]);
        u64 z0 = dup2(hs[rb + 0][k]);
        u64 z1 = dup2(hs[rb + 1][k]);
        u64 z2 = dup2(hs[rb + 2][k]);
        u64 z3 = dup2(hs[rb + 3][k]);
        a00 = ffma2(z0, wv.x, a00); a01 = ffma2(z0, wv.y, a01);
        a10 = ffma2(z1, wv.x, a10); a11 = ffma2(z1, wv.y, a11);
        a20 = ffma2(z2, wv.x, a20); a21 = ffma2(z2, wv.y, a21);
        a30 = ffma2(z3, wv.x, a30); a31 = ffma2(z3, wv.y, a31);
    }
    const ulonglong2* x2 = reinterpret_cast<const ulonglong2*>(g_x1 + (size_t)(row0 + rb) * kD);
    ulonglong2* o2 = reinterpret_cast<ulonglong2*>(out + (size_t)(row0 + rb) * kD);
    ulonglong2 xv;
    xv = x2[l];      o2[l]      = make_ulonglong2(fadd2(a00, xv.x), fadd2(a01, xv.y));
    xv = x2[32 + l]; o2[32 + l] = make_ulonglong2(fadd2(a10, xv.x), fadd2(a11, xv.y));
    xv = x2[64 + l]; o2[64 + l] = make_ulonglong2(fadd2(a20, xv.x), fadd2(a21, xv.y));
    xv = x2[96 + l]; o2[96 + l] = make_ulonglong2(fadd2(a30, xv.x), fadd2(a31, xv.y));
}

// ---------------- launch ----------------
extern "C" void kernel_launch(void* const* d_in, const int* in_sizes, int n_in,
                              void* d_out, int out_size) {
    const float* x        = (const float*)d_in[0];
    const int*   edges    = (const int*)  d_in[1];
    const float* all_dist = (const float*)d_in[2];
    const float* dist     = (const float*)d_in[3];
    const float* cdd      = (const float*)d_in[4];
    const float* css      = (const float*)d_in[5];
    const float* Wk       = (const float*)d_in[6];
    const float* bk       = (const float*)d_in[7];
    const float* Wnn      = (const float*)d_in[8];
    const float* bnn      = (const float*)d_in[9];
    const float* Wne      = (const float*)d_in[10];
    const float* bne      = (const float*)d_in[11];
    const float* Wen      = (const float*)d_in[12];
    const float* ben      = (const float*)d_in[13];
    const float* Wdd      = (const float*)d_in[14];
    const float* bdd      = (const float*)d_in[15];
    const float* Wss      = (const float*)d_in[16];
    const float* bss      = (const float*)d_in[17];
    const float* Wo       = (const float*)d_in[18];
    const float* bo       = (const float*)d_in[19];
    const float* ln1_g    = (const float*)d_in[20];
    const float* ln1_b    = (const float*)d_in[21];
    const float* ln2_g    = (const float*)d_in[22];
    const float* ln2_b    = (const float*)d_in[23];
    const float* W1       = (const float*)d_in[24];
    const float* bf1      = (const float*)d_in[25];
    const float* W2       = (const float*)d_in[26];
    const float* bf2      = (const float*)d_in[27];
    float* out = (float*)d_out;

    k_init<<<1024, 256>>>();
    k_ln_gemm<<<kN / 32, 256>>>(x, Wk, bk, ln1_g, ln1_b);
    k_mask<<<kE / 256, 256>>>(all_dist, dist, cdd, css,
                              Wnn, bnn, Wne, bne, Wen, ben, Wdd, bdd, Wss, bss);
    k_scores<<<kE / 8, 256>>>(edges);
    k_scatter<<<kE / 8, 256>>>(edges);
    k_outproj<<<kN / 32, 256>>>(x, Wo, bo);
    dim3 g6(kN / 32, 2);
    k_ff1<<<g6, 256>>>(W1, bf1, ln2_g, ln2_b);
    k_ff2<<<kN / 32, 256>>>(W2, bf2, out);
}